// round 17
// baseline (speedup 1.0000x reference)
#include <cuda_runtime.h>
#include <cuda_fp16.h>
#include <math.h>
#include <float.h>
#include <stdint.h>

// ---------------- problem constants ----------------
#define TOKENS_TOTAL (32*2048)
#define IN_DIM   128
#define HID      64
#define OUT_DIM  64
#define CODEBOOK 2048

#define TB       128
#define NTHREADS 256
#define NBLOCKS  (TOKENS_TOTAL/TB)     // 512
#define XT_STRIDE 130
#define CCH      64
#define NCH      (CODEBOOK/CCH)        // 32

#define MSG_ELEMS ((size_t)TOKENS_TOTAL*OUT_DIM)
#define IDX_OFF   MSG_ELEMS
#define LOSS_OFF  (MSG_ELEMS + TOKENS_TOTAL)

// ---------------- smem layout (word offsets) ----------------
#define OFF_E2   0                      // 2048 f (loss tree reuses +512)
#define OFF_XT   2048                   // 64 x 130 -> 10368
#define OFF_B    10368                  // 3 bufs x (hi 64x36) = 6912 -> 17280
#define B_ROW_W   36
#define B_TILE_W  (CCH*B_ROW_W)         // 2304
#define OFF_TAU  17280                  // 128 f -> 17408
#define OFF_RED  17408                  // 128 x 4 f -> 17920
#define OFF_Q    17920                  // 8 warps x 1024 u32 -> 26112
#define QCAP     1024
#define OFF_TBL  26112                  // 128 u64 = 256 w -> 26368
#define SMEM_FLOATS 26368               // 105472 B ; x2 CTAs fits 228KB

#define TAU_C (2.5f/512.0f)             // certified 2*Md coefficient + 25% headroom

// packed codebook hi tiles, FRAGMENT ORDER (r5/r10-verified)
#define CBW 32
__device__ uint4 g_cbpack4[CODEBOOK * CBW / 4];
// packed MLP weights (r15-verified)
__device__ uint4 g_wpack4[4096];
__device__ float g_e2[CODEBOOK];
__device__ int   g_e2max_bits;
__device__ float g_partial[NBLOCKS];
__device__ int   g_done = 0;

// ---------------- helpers ----------------
__device__ __forceinline__ void split_h2(float x0, float x1, uint32_t& h, uint32_t& l) {
    __half h0 = __float2half_rn(x0);
    __half h1 = __float2half_rn(x1);
    float  l0 = x0 - __half2float(h0);
    float  l1 = x1 - __half2float(h1);
    __half2 hh = __halves2half2(h0, h1);
    __half2 ll = __floats2half2_rn(l0, l1);
    h = *(uint32_t*)&hh;
    l = *(uint32_t*)&ll;
}
__device__ __forceinline__ uint32_t pack_h2(float x0, float x1) {
    __half2 hh = __floats2half2_rn(x0, x1);
    return *(uint32_t*)&hh;
}
__device__ __forceinline__ void mma16(float* c, const uint32_t* a, uint32_t b0, uint32_t b1) {
    asm volatile(
        "mma.sync.aligned.m16n8k16.row.col.f32.f16.f16.f32 "
        "{%0,%1,%2,%3}, {%4,%5,%6,%7}, {%8,%9}, {%0,%1,%2,%3};"
        : "+f"(c[0]), "+f"(c[1]), "+f"(c[2]), "+f"(c[3])
        : "r"(a[0]), "r"(a[1]), "r"(a[2]), "r"(a[3]), "r"(b0), "r"(b1));
}
__device__ __forceinline__ uint32_t fkey(float d) {
    uint32_t u = __float_as_uint(d);
    return (u & 0x80000000u) ? ~u : (u | 0x80000000u);
}

// ---------------- prep (r16 verbatim) ----------------
__global__ void prep_kernel(const float* __restrict__ cb,
                            const float* __restrict__ W1,
                            const float* __restrict__ W2,
                            const float* __restrict__ W3) {
    int gt = blockIdx.x * 256 + threadIdx.x;
    if (gt < CODEBOOK*4) {
        int c = gt >> 2, q = gt & 3;
        uint32_t hw[8], lw;
        float sq = 0.0f;
#pragma unroll
        for (int s = 0; s < 8; s++) {
            int kb = s >> 1, b = s & 1;
            int w  = kb*8 + 4*b + q;
            float x0 = __ldg(cb + (size_t)c*OUT_DIM + 2*w);
            float x1 = __ldg(cb + (size_t)c*OUT_DIM + 2*w + 1);
            split_h2(x0, x1, hw[s], lw);
            sq += x0*x0 + x1*x1;
        }
        uint32_t* hrow = (uint32_t*)g_cbpack4 + c*CBW + q*8;
        *(uint4*)(hrow)     = make_uint4(hw[0], hw[1], hw[2], hw[3]);
        *(uint4*)(hrow + 4) = make_uint4(hw[4], hw[5], hw[6], hw[7]);
        sq += __shfl_xor_sync(0xffffffffu, sq, 1);
        sq += __shfl_xor_sync(0xffffffffu, sq, 2);
        if (q == 0) {
            g_e2[c] = sq;
            atomicMax(&g_e2max_bits, __float_as_int(sq));
        }
    } else if (gt < CODEBOOK*4 + 4096) {
        int widx = gt - CODEBOOK*4;
        const float* W; int off; int local;
        if (widx < 2048)      { W = W1; off = 0;    local = widx; }
        else if (widx < 3072) { W = W2; off = 2048; local = widx - 2048; }
        else                  { W = W3; off = 3072; local = widx - 3072; }
        int lane = local & 31;
        int nb   = (local >> 5) & 7;
        int kb   = local >> 8;
        int qq = lane & 3, rr = lane >> 2;
        int n  = nb*8 + rr;
        int k0 = kb*16 + 2*qq;
        float w00 = __ldg(W + (size_t)(k0    )*64 + n);
        float w01 = __ldg(W + (size_t)(k0 + 1)*64 + n);
        float w10 = __ldg(W + (size_t)(k0 + 8)*64 + n);
        float w11 = __ldg(W + (size_t)(k0 + 9)*64 + n);
        uint32_t b0h, b0l, b1h, b1l;
        split_h2(w00, w01, b0h, b0l);
        split_h2(w10, w11, b1h, b1l);
        g_wpack4[off + local] = make_uint4(b0h, b1h, b0l, b1l);
    }
}

// ---------------- staging: hi-only uint4 copy ----------------
__device__ __forceinline__ void b_ldg(int ch, int tid, uint4* v) {
    const uint4* hb = g_cbpack4 + (size_t)ch*CCH*(CBW/4);
    v[0] = __ldg(hb + tid);
    v[1] = __ldg(hb + tid + 256);
}
__device__ __forceinline__ void b_sts(uint32_t* bbuf, int tid, const uint4* v) {
#pragma unroll
    for (int i = 0; i < 2; i++) {
        int idx = tid + i*256;
        int c0 = idx >> 3, sub = idx & 7;
        *(uint4*)(bbuf + c0*B_ROW_W + sub*4) = v[i];
    }
}

// ---------------- exact fp32 rescore (r7-verified) ----------------
__device__ __forceinline__ float rescore(const float* __restrict__ cb, const float* xsT,
                                          const float* e2s, int t, int c) {
    const float4* er = (const float4*)(cb + (size_t)c * OUT_DIM);
    float s = 0.0f;
#pragma unroll
    for (int j4 = 0; j4 < 16; j4++) {
        float4 e4 = __ldg(er + j4);
        int j = j4*4;
        s = fmaf(e4.x, xsT[(j  )*XT_STRIDE + t], s);
        s = fmaf(e4.y, xsT[(j+1)*XT_STRIDE + t], s);
        s = fmaf(e4.z, xsT[(j+2)*XT_STRIDE + t], s);
        s = fmaf(e4.w, xsT[(j+3)*XT_STRIDE + t], s);
    }
    return fmaf(-2.0f, s, e2s[c]);
}

// ---------------- fused kernel ----------------
__global__ void __launch_bounds__(NTHREADS, 2)
vq_main(const float* __restrict__ obs,
        const float* __restrict__ W1, const float* __restrict__ b1,
        const float* __restrict__ W2, const float* __restrict__ b2,
        const float* __restrict__ W3, const float* __restrict__ b3,
        const float* __restrict__ cb,
        float* __restrict__ out)
{
    extern __shared__ float sm[];
    __shared__ int wq_cnt[8];
    __shared__ int isLast;
    const int tid  = threadIdx.x;
    const int wid  = tid >> 5;
    const int lane = tid & 31;
    const int r    = lane >> 2;
    const int q    = lane & 3;
    const int tok0 = blockIdx.x * TB;
    const int tokw = wid * 16;

    for (int i = tid; i < CODEBOOK; i += NTHREADS) sm[OFF_E2 + i] = g_e2[i];

    // ================= MLP on tensor cores (r15/16 verbatim) =================
    {
        float acc[8][4];
#pragma unroll
        for (int nb = 0; nb < 8; nb++)
#pragma unroll
            for (int j = 0; j < 4; j++) acc[nb][j] = 0.f;

        const float* r0 = obs + (size_t)(tok0 + tokw + r)*IN_DIM;
        const float* r8 = r0 + 8*IN_DIM;

#pragma unroll
        for (int kb = 0; kb < 8; kb++) {
            int k0 = kb*16 + 2*q;
            float2 p0 = *(const float2*)(r0 + k0);
            float2 p1 = *(const float2*)(r8 + k0);
            float2 p2 = *(const float2*)(r0 + k0 + 8);
            float2 p3 = *(const float2*)(r8 + k0 + 8);
            uint32_t ah[4], al[4];
            split_h2(p0.x, p0.y, ah[0], al[0]);
            split_h2(p1.x, p1.y, ah[1], al[1]);
            split_h2(p2.x, p2.y, ah[2], al[2]);
            split_h2(p3.x, p3.y, ah[3], al[3]);
#pragma unroll
            for (int nb = 0; nb < 8; nb++) {
                uint4 wv = __ldg(g_wpack4 + (kb*8 + nb)*32 + lane);
                mma16(acc[nb], ah, wv.x, wv.y);
                mma16(acc[nb], ah, wv.z, wv.w);
                mma16(acc[nb], al, wv.x, wv.y);
            }
        }

        uint32_t Fh[4][4], Fl[4][4];
#pragma unroll
        for (int kb2 = 0; kb2 < 4; kb2++)
#pragma unroll
            for (int hf = 0; hf < 2; hf++) {
                int nb = kb2*2 + hf;
                float bb0 = __ldg(b1 + nb*8 + 2*q);
                float bb1 = __ldg(b1 + nb*8 + 2*q + 1);
                float h0 = fmaxf(acc[nb][0] + bb0, 0.f);
                float h1 = fmaxf(acc[nb][1] + bb1, 0.f);
                float h2 = fmaxf(acc[nb][2] + bb0, 0.f);
                float h3 = fmaxf(acc[nb][3] + bb1, 0.f);
                split_h2(h0, h1, Fh[kb2][hf*2],     Fl[kb2][hf*2]);
                split_h2(h2, h3, Fh[kb2][hf*2 + 1], Fl[kb2][hf*2 + 1]);
            }

        float acc2[8][4];
#pragma unroll
        for (int nb = 0; nb < 8; nb++)
#pragma unroll
            for (int j = 0; j < 4; j++) acc2[nb][j] = 0.f;
#pragma unroll
        for (int kb = 0; kb < 4; kb++)
#pragma unroll
            for (int nb = 0; nb < 8; nb++) {
                uint4 wv = __ldg(g_wpack4 + 2048 + (kb*8 + nb)*32 + lane);
                mma16(acc2[nb], Fh[kb], wv.x, wv.y);
                mma16(acc2[nb], Fh[kb], wv.z, wv.w);
                mma16(acc2[nb], Fl[kb], wv.x, wv.y);
            }

#pragma unroll
        for (int kb2 = 0; kb2 < 4; kb2++)
#pragma unroll
            for (int hf = 0; hf < 2; hf++) {
                int nb = kb2*2 + hf;
                float bb0 = __ldg(b2 + nb*8 + 2*q);
                float bb1 = __ldg(b2 + nb*8 + 2*q + 1);
                float h0 = fmaxf(acc2[nb][0] + bb0, 0.f);
                float h1 = fmaxf(acc2[nb][1] + bb1, 0.f);
                float h2 = fmaxf(acc2[nb][2] + bb0, 0.f);
                float h3 = fmaxf(acc2[nb][3] + bb1, 0.f);
                split_h2(h0, h1, Fh[kb2][hf*2],     Fl[kb2][hf*2]);
                split_h2(h2, h3, Fh[kb2][hf*2 + 1], Fl[kb2][hf*2 + 1]);
            }

#pragma unroll
        for (int nb = 0; nb < 8; nb++)
#pragma unroll
            for (int j = 0; j < 4; j++) acc[nb][j] = 0.f;
#pragma unroll
        for (int kb = 0; kb < 4; kb++)
#pragma unroll
            for (int nb = 0; nb < 8; nb++) {
                uint4 wv = __ldg(g_wpack4 + 3072 + (kb*8 + nb)*32 + lane);
                mma16(acc[nb], Fh[kb], wv.x, wv.y);
                mma16(acc[nb], Fh[kb], wv.z, wv.w);
                mma16(acc[nb], Fl[kb], wv.x, wv.y);
            }

        float* base = sm + OFF_XT;
#pragma unroll
        for (int nb = 0; nb < 8; nb++) {
            int n0 = nb*8 + 2*q;
            float bb0 = __ldg(b3 + n0);
            float bb1 = __ldg(b3 + n0 + 1);
            base[(n0    )*XT_STRIDE + tokw + r]     = acc[nb][0] + bb0;
            base[(n0 + 1)*XT_STRIDE + tokw + r]     = acc[nb][1] + bb1;
            base[(n0    )*XT_STRIDE + tokw + r + 8] = acc[nb][2] + bb0;
            base[(n0 + 1)*XT_STRIDE + tokw + r + 8] = acc[nb][3] + bb1;
        }
    }
    __syncthreads();

    // ========== A fragments: FOUR m16 tiles per warp (64 tokens), hi only ==========
    const float* xsT = sm + OFF_XT;
    const int wtile    = wid & 1;        // token half: 0 -> tokens 0..63, 1 -> 64..127
    const int wquarter = wid >> 1;       // code quarter within chunk (16 codes)
    const int tokw64   = wtile * 64;

    uint32_t Ah[4][4][4];
#pragma unroll
    for (int tl = 0; tl < 4; tl++)
#pragma unroll
        for (int kb = 0; kb < 4; kb++) {
            int k0 = kb*16;
            const float* x0 = xsT + tokw64 + tl*16;
            Ah[tl][kb][0] = pack_h2(x0[(k0 + 2*q    )*XT_STRIDE + r],
                                    x0[(k0 + 2*q + 1)*XT_STRIDE + r]);
            Ah[tl][kb][1] = pack_h2(x0[(k0 + 2*q    )*XT_STRIDE + r + 8],
                                    x0[(k0 + 2*q + 1)*XT_STRIDE + r + 8]);
            Ah[tl][kb][2] = pack_h2(x0[(k0 + 2*q + 8)*XT_STRIDE + r],
                                    x0[(k0 + 2*q + 9)*XT_STRIDE + r]);
            Ah[tl][kb][3] = pack_h2(x0[(k0 + 2*q + 8)*XT_STRIDE + r + 8],
                                    x0[(k0 + 2*q + 9)*XT_STRIDE + r + 8]);
        }

    unsigned long long* tbl = (unsigned long long*)(sm + OFF_TBL);
    if (tid < TB) tbl[tid] = 0xFFFFFFFFFFFFFFFFull;
    if (tid < 8)  wq_cnt[tid] = 0;

    uint32_t* bw = (uint32_t*)(sm + OFF_B);
    const float* e2s = sm + OFF_E2;

    // ================= PASS 1: hh sweep, per-pair min =================
    float bmin[8];
#pragma unroll
    for (int p = 0; p < 8; p++) bmin[p] = FLT_MAX;

    {
        uint4 st[2];
        b_ldg(0, tid, st);
        b_sts(bw, tid, st);
        __syncthreads();
    }
    for (int ch = 0; ch < NCH; ch++) {
        const int buf = ch % 3;
        uint4 pv[2];
        const bool more = (ch + 1 < NCH);
        if (more) b_ldg(ch + 1, tid, pv);

        const uint32_t* bb = bw + buf*B_TILE_W;
#pragma unroll
        for (int cb8 = 0; cb8 < 2; cb8++) {
            const uint32_t* pr = bb + (wquarter*16 + cb8*8 + r)*B_ROW_W + q*8;
            uint4 h01 = *(const uint4*)(pr);
            uint4 h23 = *(const uint4*)(pr + 4);

            float acc[4][4] = {{0,0,0,0},{0,0,0,0},{0,0,0,0},{0,0,0,0}};
#pragma unroll
            for (int tl = 0; tl < 4; tl++) {
                mma16(acc[tl], Ah[tl][0], h01.x, h01.y);
                mma16(acc[tl], Ah[tl][1], h01.z, h01.w);
                mma16(acc[tl], Ah[tl][2], h23.x, h23.y);
                mma16(acc[tl], Ah[tl][3], h23.z, h23.w);
            }
            int code0 = ch*CCH + wquarter*16 + cb8*8 + 2*q;
            float e20 = e2s[code0], e21 = e2s[code0 + 1];
#pragma unroll
            for (int tl = 0; tl < 4; tl++) {
                bmin[tl*2]     = fminf(bmin[tl*2],
                                       fminf(fmaf(-2.f, acc[tl][0], e20),
                                             fmaf(-2.f, acc[tl][1], e21)));
                bmin[tl*2 + 1] = fminf(bmin[tl*2 + 1],
                                       fminf(fmaf(-2.f, acc[tl][2], e20),
                                             fmaf(-2.f, acc[tl][3], e21)));
            }
        }

        if (more) b_sts(bw + ((ch + 1) % 3)*B_TILE_W, tid, pv);
        __syncthreads();
    }

    // ---- inter-pass: per-token tau (fixed threshold) ----
#pragma unroll
    for (int m = 1; m <= 2; m <<= 1)
#pragma unroll
        for (int p = 0; p < 8; p++)
            bmin[p] = fminf(bmin[p], __shfl_xor_sync(0xffffffffu, bmin[p], m));
    float* sRedMin = sm + OFF_RED;
    if (q == 0) {
#pragma unroll
        for (int p = 0; p < 8; p++) {
            int t = tokw64 + (p >> 1)*16 + r + 8*(p & 1);
            sRedMin[t*4 + wquarter] = bmin[p];
        }
    }
    __syncthreads();
    if (tid < TB) {
        float m1 = fminf(fminf(sRedMin[tid*4], sRedMin[tid*4 + 1]),
                         fminf(sRedMin[tid*4 + 2], sRedMin[tid*4 + 3]));
        float nx = 0.f;
#pragma unroll
        for (int j = 0; j < OUT_DIM; j++) {
            float xv = xsT[j*XT_STRIDE + tid];
            nx = fmaf(xv, xv, nx);
        }
        float emax = sqrtf(__int_as_float(g_e2max_bits));
        sm[OFF_TAU + tid] = m1 + TAU_C * sqrtf(nx) * emax + 1e-4f;
    }
    {
        uint4 st[2];
        b_ldg(0, tid, st);
        b_sts(bw, tid, st);
    }
    __syncthreads();

    // ================= PASS 2: identical hh sweep, enqueue d <= tau =================
    float tauR[8];
#pragma unroll
    for (int p = 0; p < 8; p++)
        tauR[p] = sm[OFF_TAU + tokw64 + (p >> 1)*16 + r + 8*(p & 1)];
    uint32_t* wq = (uint32_t*)(sm + OFF_Q) + wid*QCAP;

    for (int ch = 0; ch < NCH; ch++) {
        const int buf = ch % 3;
        uint4 pv[2];
        const bool more = (ch + 1 < NCH);
        if (more) b_ldg(ch + 1, tid, pv);

        const uint32_t* bb = bw + buf*B_TILE_W;
#pragma unroll
        for (int cb8 = 0; cb8 < 2; cb8++) {
            const uint32_t* pr = bb + (wquarter*16 + cb8*8 + r)*B_ROW_W + q*8;
            uint4 h01 = *(const uint4*)(pr);
            uint4 h23 = *(const uint4*)(pr + 4);

            float acc[4][4] = {{0,0,0,0},{0,0,0,0},{0,0,0,0},{0,0,0,0}};
#pragma unroll
            for (int tl = 0; tl < 4; tl++) {
                mma16(acc[tl], Ah[tl][0], h01.x, h01.y);
                mma16(acc[tl], Ah[tl][1], h01.z, h01.w);
                mma16(acc[tl], Ah[tl][2], h23.x, h23.y);
                mma16(acc[tl], Ah[tl][3], h23.z, h23.w);
            }
            int code0 = ch*CCH + wquarter*16 + cb8*8 + 2*q;
            float e20 = e2s[code0], e21 = e2s[code0 + 1];

            float d[4][4];
            bool hit = false;
#pragma unroll
            for (int tl = 0; tl < 4; tl++) {
                d[tl][0] = fmaf(-2.f, acc[tl][0], e20);
                d[tl][1] = fmaf(-2.f, acc[tl][1], e21);
                d[tl][2] = fmaf(-2.f, acc[tl][2], e20);
                d[tl][3] = fmaf(-2.f, acc[tl][3], e21);
                float t0 = tauR[tl*2], t1 = tauR[tl*2 + 1];
                hit |= (d[tl][0] <= t0) | (d[tl][1] <= t0)
                     | (d[tl][2] <= t1) | (d[tl][3] <= t1);
            }
            if (__ballot_sync(0xffffffffu, hit)) {
#pragma unroll
                for (int tl = 0; tl < 4; tl++) {
                    int t0 = tokw64 + tl*16 + r;
                    int t1 = t0 + 8;
                    float ta = tauR[tl*2], tb = tauR[tl*2 + 1];
                    if (d[tl][0] <= ta) { int pos = atomicAdd(&wq_cnt[wid], 1);
                        if (pos < QCAP) wq[pos] = ((uint32_t)t0 << 11) | (uint32_t)code0; }
                    if (d[tl][1] <= ta) { int pos = atomicAdd(&wq_cnt[wid], 1);
                        if (pos < QCAP) wq[pos] = ((uint32_t)t0 << 11) | (uint32_t)(code0 + 1); }
                    if (d[tl][2] <= tb) { int pos = atomicAdd(&wq_cnt[wid], 1);
                        if (pos < QCAP) wq[pos] = ((uint32_t)t1 << 11) | (uint32_t)code0; }
                    if (d[tl][3] <= tb) { int pos = atomicAdd(&wq_cnt[wid], 1);
                        if (pos < QCAP) wq[pos] = ((uint32_t)t1 << 11) | (uint32_t)(code0 + 1); }
                }
            }
        }

        if (more) b_sts(bw + ((ch + 1) % 3)*B_TILE_W, tid, pv);
        __syncthreads();
    }

    // ================= exact rescore of candidates =================
    int nq = wq_cnt[wid];
    int n  = nq < QCAP ? nq : QCAP;
    for (int i = lane; i < n; i += 32) {
        uint32_t e = wq[i];
        int t = e >> 11, c = e & 0x7FF;
        float dd = rescore(cb, xsT, e2s, t, c);
        unsigned long long key = ((unsigned long long)fkey(dd) << 32) | (unsigned)c;
        atomicMin(&tbl[t], key);
    }
    if (nq > QCAP) {   // overflow: exhaustive exact fallback over this warp's 64 tokens
        for (int s = 0; s < 64; s++) {
            int t = tokw64 + s;
            for (int c = lane; c < CODEBOOK; c += 32) {
                float dd = rescore(cb, xsT, e2s, t, c);
                unsigned long long key = ((unsigned long long)fkey(dd) << 32) | (unsigned)c;
                atomicMin(&tbl[t], key);
            }
        }
    }
    __syncthreads();

    // ---- idx write ----
    int* sIdx = (int*)(sm + OFF_RED);
    if (tid < TB) {
        int bc = (int)(tbl[tid] & 0xFFFFFFFFull);
        sIdx[tid] = bc;
        out[IDX_OFF + (size_t)(tok0 + tid)] = (float)bc;
    }
    __syncthreads();

    // ---- msg write + commitment-loss partial ----
    float part = 0.0f;
    for (int f = tid; f < TB*OUT_DIM; f += NTHREADS) {
        int t = f >> 6, j = f & 63;
        int c = sIdx[t];
        float qv = __ldg(cb + (size_t)c * OUT_DIM + j);
        float xv = xsT[j*XT_STRIDE + t];
        out[(size_t)(tok0 + t)*OUT_DIM + j] = xv + (qv - xv);
        float dd = qv - xv;
        part += dd * dd;
    }
#pragma unroll
    for (int o = 16; o > 0; o >>= 1)
        part += __shfl_down_sync(0xffffffffu, part, o);
    __shared__ float swred[8];
    if ((tid & 31) == 0) swred[tid >> 5] = part;
    __syncthreads();
    if (tid == 0) {
        float s = 0.0f;
#pragma unroll
        for (int w = 0; w < 8; w++) s += swred[w];
        g_partial[blockIdx.x] = s;
        __threadfence();
        isLast = (atomicAdd(&g_done, 1) == NBLOCKS - 1);
    }
    __syncthreads();

    if (isLast) {
        volatile float* gp = g_partial;
        float* red = sm + 512;
        red[tid] = gp[tid] + gp[tid + NTHREADS];
        __syncthreads();
        for (int o = NTHREADS/2; o > 0; o >>= 1) {
            if (tid < o) red[tid] += red[tid + o];
            __syncthreads();
        }
        if (tid == 0) {
            out[LOSS_OFF] = red[0] * (1.0f / (float)MSG_ELEMS);
            g_done = 0;
        }
    }
}

extern "C" void kernel_launch(void* const* d_in, const int* in_sizes, int n_in,
                              void* d_out, int out_size)
{
    const float* obs = (const float*)d_in[0];
    const float* W1  = (const float*)d_in[1];
    const float* b1  = (const float*)d_in[2];
    const float* W2  = (const float*)d_in[3];
    const float* b2  = (const float*)d_in[4];
    const float* W3  = (const float*)d_in[5];
    const float* b3  = (const float*)d_in[6];
    const float* cb  = (const float*)d_in[7];
    float* out = (float*)d_out;

    cudaFuncSetAttribute(vq_main, cudaFuncAttributeMaxDynamicSharedMemorySize,
                         SMEM_FLOATS * (int)sizeof(float));

    prep_kernel<<<(CODEBOOK*4 + 4096 + 255)/256, 256>>>(cb, W1, W2, W3);
    vq_main<<<NBLOCKS, NTHREADS, SMEM_FLOATS * sizeof(float)>>>(
        obs, W1, b1, W2, b2, W3, b3, cb, out);
}